// round 1
// baseline (speedup 1.0000x reference)
#include <cuda_runtime.h>
#include <cuda_bf16.h>
#include <mma.h>
#include <math.h>

using namespace nvcuda;

// ---------------- problem constants ----------------
#define NTOK   65536      // B*S = 8*8192
#define BATCH  8
#define SEQ    8192
#define DMODEL 512
#define NHEAD  8
#define NKV    2
#define DHEAD  64
#define MFEAT  64
#define DFF    2048
#define NCLS   2
#define EPSV   1e-6f

// ---------------- scratch (static device allocations only) ----------------
__device__ float g_x  [NTOK * DMODEL];   // residual stream
__device__ float g_h  [NTOK * DMODEL];   // rmsnorm output (h and h2)
__device__ float g_q  [NTOK * NHEAD * DHEAD];
__device__ float g_k  [NTOK * NKV  * DHEAD];
__device__ float g_v  [NTOK * NKV  * DHEAD];
__device__ float g_pq [NTOK * NHEAD * MFEAT];
__device__ float g_pk [NTOK * NKV  * MFEAT];
__device__ float g_att[NTOK * DMODEL];
__device__ float g_u  [NTOK * DFF];
__device__ float g_gu [NTOK * DFF];
__device__ float g_kvp[128 * 64 * 65];   // 16 pairs * 8 chunks, [64][65] (col 64 = z)
__device__ float g_kv [16 * 64 * 65];
__device__ float g_xm [BATCH * DMODEL];

// ---------------- generic tf32 WMMA GEMM ----------------
// C[M,Nc] = A[M,K] @ B[K,Nc], with fused epilogue.
// epi: 0 = none, 1 = C = acc + X, 2 = C = exp(-|acc|), 3 = C = silu(acc) * X
#define EPI_NONE   0
#define EPI_RES    1
#define EPI_EXPABS 2
#define EPI_SILU   3

#define BM 128
#define BN 64
#define BKT 32
#define LDA 36   // BK+4 (144B, mult of 16)
#define LDB 68   // BN+4 (272B, mult of 16)
#define LDCS 68

__global__ __launch_bounds__(256) void gemm_tf32_kernel(
    const float* __restrict__ A, const float* __restrict__ B,
    float* __restrict__ C, const float* __restrict__ X,
    int M, int K, int Nc, int epi)
{
    __shared__ float smem[BM * LDCS];            // 34816 B; aliased As|Bs then Cs
    float* As = smem;                            // 128*36 = 4608 floats
    float* Bs = smem + BM * LDA;                 // 32*68  = 2176 floats (total 6784 <= 8704)

    const int tid  = threadIdx.x;
    const int bm   = blockIdx.x * BM;
    const int bn   = blockIdx.y * BN;
    const int warp = tid >> 5;
    const int wm   = (warp & 3) * 32;
    const int wn   = (warp >> 2) * 32;

    wmma::fragment<wmma::accumulator, 16, 16, 8, float> c[2][2];
#pragma unroll
    for (int i = 0; i < 2; i++)
#pragma unroll
        for (int j = 0; j < 2; j++) wmma::fill_fragment(c[i][j], 0.0f);

    for (int kt = 0; kt < K; kt += BKT) {
        // stage A tile: 128x32
#pragma unroll
        for (int i = 0; i < 4; i++) {
            int r  = (tid >> 3) + 32 * i;
            int cc = (tid & 7) * 4;
            float4 vv = *(const float4*)&A[(size_t)(bm + r) * K + kt + cc];
            *(float4*)&As[r * LDA + cc] = vv;
        }
        // stage B tile: 32x64
#pragma unroll
        for (int i = 0; i < 2; i++) {
            int idx = tid + i * 256;
            int r   = idx >> 4;
            int cc  = (idx & 15) * 4;
            float4 vv = *(const float4*)&B[(size_t)(kt + r) * Nc + bn + cc];
            *(float4*)&Bs[r * LDB + cc] = vv;
        }
        __syncthreads();

#pragma unroll
        for (int kk = 0; kk < BKT; kk += 8) {
            wmma::fragment<wmma::matrix_a, 16, 16, 8, wmma::precision::tf32, wmma::row_major> a[2];
            wmma::fragment<wmma::matrix_b, 16, 16, 8, wmma::precision::tf32, wmma::row_major> b[2];
#pragma unroll
            for (int i = 0; i < 2; i++) {
                wmma::load_matrix_sync(a[i], &As[(wm + i * 16) * LDA + kk], LDA);
#pragma unroll
                for (int t = 0; t < a[i].num_elements; t++)
                    a[i].x[t] = wmma::__float_to_tf32(a[i].x[t]);
            }
#pragma unroll
            for (int j = 0; j < 2; j++) {
                wmma::load_matrix_sync(b[j], &Bs[kk * LDB + wn + j * 16], LDB);
#pragma unroll
                for (int t = 0; t < b[j].num_elements; t++)
                    b[j].x[t] = wmma::__float_to_tf32(b[j].x[t]);
            }
#pragma unroll
            for (int i = 0; i < 2; i++)
#pragma unroll
                for (int j = 0; j < 2; j++)
                    wmma::mma_sync(c[i][j], a[i], b[j], c[i][j]);
        }
        __syncthreads();
    }

    // stage accumulators to smem, then fused epilogue -> global
    float* Cs = smem;
#pragma unroll
    for (int i = 0; i < 2; i++)
#pragma unroll
        for (int j = 0; j < 2; j++)
            wmma::store_matrix_sync(&Cs[(wm + i * 16) * LDCS + wn + j * 16], c[i][j],
                                    LDCS, wmma::mem_row_major);
    __syncthreads();

#pragma unroll
    for (int i = 0; i < 8; i++) {
        int e  = tid + i * 256;        // 0..2047 float4s
        int r  = e >> 4;
        int cc = (e & 15) * 4;
        float4 vv = *(float4*)&Cs[r * LDCS + cc];
        size_t gidx = (size_t)(bm + r) * Nc + bn + cc;
        if (epi == EPI_RES) {
            float4 xv = *(const float4*)&X[gidx];
            vv.x += xv.x; vv.y += xv.y; vv.z += xv.z; vv.w += xv.w;
        } else if (epi == EPI_EXPABS) {
            vv.x = expf(-fabsf(vv.x)); vv.y = expf(-fabsf(vv.y));
            vv.z = expf(-fabsf(vv.z)); vv.w = expf(-fabsf(vv.w));
        } else if (epi == EPI_SILU) {
            float4 uv = *(const float4*)&X[gidx];
            vv.x = vv.x / (1.0f + expf(-vv.x)) * uv.x;
            vv.y = vv.y / (1.0f + expf(-vv.y)) * uv.y;
            vv.z = vv.z / (1.0f + expf(-vv.z)) * uv.z;
            vv.w = vv.w / (1.0f + expf(-vv.w)) * uv.w;
        }
        *(float4*)&C[gidx] = vv;
    }
}

// ---------------- gather + rmsnorm (also plain rmsnorm) ----------------
// if ids != nullptr: src row = emb[ids[token]], also writes xout.
__global__ __launch_bounds__(128) void gather_rmsnorm_kernel(
    const int* __restrict__ ids, const float* __restrict__ emb,
    const float* __restrict__ xin, const float* __restrict__ g,
    float* __restrict__ xout, float* __restrict__ h)
{
    int token = blockIdx.x;
    const float* src = ids ? (emb + (size_t)ids[token] * DMODEL)
                           : (xin + (size_t)token * DMODEL);
    int c = threadIdx.x * 4;
    float4 v = *(const float4*)&src[c];
    float ss = v.x * v.x + v.y * v.y + v.z * v.z + v.w * v.w;
#pragma unroll
    for (int off = 16; off > 0; off >>= 1) ss += __shfl_xor_sync(0xffffffffu, ss, off);
    __shared__ float sred[4];
    int warp = threadIdx.x >> 5, lane = threadIdx.x & 31;
    if (lane == 0) sred[warp] = ss;
    __syncthreads();
    float tot = sred[0] + sred[1] + sred[2] + sred[3];
    float scale = rsqrtf(tot * (1.0f / DMODEL) + EPSV);
    float4 gv = *(const float4*)&g[c];
    float4 o;
    o.x = v.x * scale * gv.x; o.y = v.y * scale * gv.y;
    o.z = v.z * scale * gv.z; o.w = v.w * scale * gv.w;
    if (xout) *(float4*)&xout[(size_t)token * DMODEL + c] = v;
    *(float4*)&h[(size_t)token * DMODEL + c] = o;
}

// ---------------- kv state: kv[b,kh,m,d] = sum_s pk*v ; col 64 = z ----------------
__global__ __launch_bounds__(256) void kv_partial_kernel(
    const float* __restrict__ pk, const float* __restrict__ v, float* __restrict__ kvp)
{
    int pair = blockIdx.x;            // b*2+kh
    int chunk = blockIdx.y;           // 0..7
    int b = pair >> 1, kh = pair & 1;
    int tid = threadIdx.x;
    int ti = tid >> 4, tj = tid & 15; // 16x16 thread grid, 4x4 micro-tile
    float acc[4][4];
    float zacc[4];
#pragma unroll
    for (int a = 0; a < 4; a++) { zacc[a] = 0.f;
#pragma unroll
        for (int bb = 0; bb < 4; bb++) acc[a][bb] = 0.f; }

    __shared__ float spk[4][64], sv[4][64];
    int s0 = chunk * 1024;
    int tok = tid >> 6, lane = tid & 63;
    for (int sb = 0; sb < 1024; sb += 4) {
        int token = b * SEQ + s0 + sb + tok;
        size_t base = ((size_t)token * NKV + kh) * 64 + lane;
        spk[tok][lane] = pk[base];
        sv[tok][lane]  = v[base];
        __syncthreads();
#pragma unroll
        for (int t = 0; t < 4; t++) {
            float pm[4], vd[4];
#pragma unroll
            for (int mm = 0; mm < 4; mm++) pm[mm] = spk[t][ti * 4 + mm];
#pragma unroll
            for (int dd = 0; dd < 4; dd++) vd[dd] = sv[t][tj * 4 + dd];
#pragma unroll
            for (int mm = 0; mm < 4; mm++) {
#pragma unroll
                for (int dd = 0; dd < 4; dd++) acc[mm][dd] = fmaf(pm[mm], vd[dd], acc[mm][dd]);
                if (tj == 0) zacc[mm] += pm[mm];
            }
        }
        __syncthreads();
    }
    int pc = pair * 8 + chunk;
#pragma unroll
    for (int mm = 0; mm < 4; mm++) {
#pragma unroll
        for (int dd = 0; dd < 4; dd++)
            kvp[(size_t)pc * 4160 + (ti * 4 + mm) * 65 + tj * 4 + dd] = acc[mm][dd];
        if (tj == 0) kvp[(size_t)pc * 4160 + (ti * 4 + mm) * 65 + 64] = zacc[mm];
    }
}

__global__ __launch_bounds__(256) void kv_reduce_kernel(
    const float* __restrict__ kvp, float* __restrict__ kv)
{
    int pair = blockIdx.x;
    for (int idx = threadIdx.x; idx < 4160; idx += 256) {
        float s = 0.f;
#pragma unroll
        for (int c = 0; c < 8; c++) s += kvp[(size_t)(pair * 8 + c) * 4160 + idx];
        kv[(size_t)pair * 4160 + idx] = s;
    }
}

// ---------------- num/den: attn = (pq @ kv) / (pq @ z + eps) ----------------
__global__ __launch_bounds__(256) void numden_kernel(
    const float* __restrict__ pq, const float* __restrict__ kvg, float* __restrict__ att)
{
    int b = blockIdx.y;
    __shared__ float skv[2 * 64 * 65];   // 33280 B
    __shared__ float spq[4][64];
    for (int idx = threadIdx.x; idx < 8320; idx += 256)
        skv[idx] = kvg[(size_t)b * 8320 + idx];
    __syncthreads();

    int group = threadIdx.x >> 6, lane = threadIdx.x & 63;
    int base = blockIdx.x * 128;                 // token-head index within batch b
    for (int it = 0; it < 32; it++) {
        int th = base + it * 4 + group;          // th = s*8 + h
        size_t row = ((size_t)b * (SEQ * NHEAD) + th) * 64;
        spq[group][lane] = pq[row + lane];
        __syncthreads();
        int h = th & 7;
        const float* kvh = &skv[(h >> 2) * 4160];
        float num = 0.f, den = 0.f;
#pragma unroll
        for (int m = 0; m < 64; m++) {
            float p = spq[group][m];
            num = fmaf(p, kvh[m * 65 + lane], num);
            den = fmaf(p, kvh[m * 65 + 64], den);
        }
        att[row + lane] = num / (den + EPSV);
        __syncthreads();
    }
}

// ---------------- mean pool over sequence ----------------
__global__ __launch_bounds__(256) void pool_kernel(
    const float* __restrict__ x, float* __restrict__ xm)
{
    int b = blockIdx.y;
    int c = blockIdx.x * 64 + (threadIdx.x & 63);
    int part = threadIdx.x >> 6;
    float s = 0.f;
    for (int t = part; t < SEQ; t += 4)
        s += x[((size_t)b * SEQ + t) * DMODEL + c];
    __shared__ float red[4][64];
    red[part][threadIdx.x & 63] = s;
    __syncthreads();
    if (part == 0) {
        int l = threadIdx.x & 63;
        xm[b * DMODEL + c] = red[0][l] + red[1][l] + red[2][l] + red[3][l];
    }
}

// ---------------- classifier head ----------------
__global__ __launch_bounds__(512) void head_kernel(
    const float* __restrict__ xm, const float* __restrict__ Wc,
    const float* __restrict__ bc, float* __restrict__ out)
{
    int warp = threadIdx.x >> 5, lane = threadIdx.x & 31;
    int b = warp >> 1, cls = warp & 1;
    float s = 0.f;
    for (int d = lane; d < DMODEL; d += 32)
        s += xm[b * DMODEL + d] * Wc[d * NCLS + cls];
#pragma unroll
    for (int off = 16; off > 0; off >>= 1) s += __shfl_xor_sync(0xffffffffu, s, off);
    if (lane == 0) out[b * NCLS + cls] = s * (1.0f / SEQ) + bc[cls];
}

// ---------------- launch ----------------
static void gemm(const float* A, const float* B, float* C, const float* X,
                 int M, int K, int Nc, int epi)
{
    dim3 grid(M / BM, Nc / BN);
    gemm_tf32_kernel<<<grid, 256>>>(A, B, C, X, M, K, Nc, epi);
}

extern "C" void kernel_launch(void* const* d_in, const int* in_sizes, int n_in,
                              void* d_out, int out_size)
{
    (void)in_sizes; (void)n_in; (void)out_size;
    const int*   ids  = (const int*)  d_in[0];
    const float* emb  = (const float*)d_in[1];
    const float* Wq   = (const float*)d_in[2];
    const float* Wk   = (const float*)d_in[3];
    const float* Wv   = (const float*)d_in[4];
    const float* Wphi = (const float*)d_in[5];
    const float* Wo   = (const float*)d_in[6];
    const float* g1   = (const float*)d_in[7];
    const float* g2   = (const float*)d_in[8];
    const float* Wg   = (const float*)d_in[9];
    const float* Wu   = (const float*)d_in[10];
    const float* Wd   = (const float*)d_in[11];
    const float* Wc   = (const float*)d_in[12];
    const float* bc   = (const float*)d_in[13];
    float* out = (float*)d_out;

    float *x, *h, *q, *k, *v, *pq, *pk, *att, *u, *gu, *kvp, *kv, *xm;
    cudaGetSymbolAddress((void**)&x,   g_x);
    cudaGetSymbolAddress((void**)&h,   g_h);
    cudaGetSymbolAddress((void**)&q,   g_q);
    cudaGetSymbolAddress((void**)&k,   g_k);
    cudaGetSymbolAddress((void**)&v,   g_v);
    cudaGetSymbolAddress((void**)&pq,  g_pq);
    cudaGetSymbolAddress((void**)&pk,  g_pk);
    cudaGetSymbolAddress((void**)&att, g_att);
    cudaGetSymbolAddress((void**)&u,   g_u);
    cudaGetSymbolAddress((void**)&gu,  g_gu);
    cudaGetSymbolAddress((void**)&kvp, g_kvp);
    cudaGetSymbolAddress((void**)&kv,  g_kv);
    cudaGetSymbolAddress((void**)&xm,  g_xm);

    // 1. embedding gather + rmsnorm (writes x and h)
    gather_rmsnorm_kernel<<<NTOK, 128>>>(ids, emb, nullptr, g1, x, h);

    // 2. q/k/v projections
    gemm(h, Wq, q, nullptr, NTOK, DMODEL, NHEAD * DHEAD, EPI_NONE);
    gemm(h, Wk, k, nullptr, NTOK, DMODEL, NKV * DHEAD, EPI_NONE);
    gemm(h, Wv, v, nullptr, NTOK, DMODEL, NKV * DHEAD, EPI_NONE);

    // 3. Laplacian feature maps: phi = exp(-|u @ Wphi|) as reshaped GEMMs
    gemm(q, Wphi, pq, nullptr, NTOK * NHEAD, DHEAD, MFEAT, EPI_EXPABS);
    gemm(k, Wphi, pk, nullptr, NTOK * NKV,  DHEAD, MFEAT, EPI_EXPABS);

    // 4. global kv state + normalizer (deterministic 2-stage reduction)
    {
        dim3 gp(BATCH * NKV, 8);
        kv_partial_kernel<<<gp, 256>>>(pk, v, kvp);
        kv_reduce_kernel<<<BATCH * NKV, 256>>>(kvp, kv);
    }

    // 5. num/den -> attn
    {
        dim3 gn(SEQ * NHEAD / 128, BATCH);
        numden_kernel<<<gn, 256>>>(pq, kv, att);
    }

    // 6. output projection + residual (in-place on x)
    gemm(att, Wo, x, x, NTOK, DMODEL, DMODEL, EPI_RES);

    // 7. pre-FFN rmsnorm
    gather_rmsnorm_kernel<<<NTOK, 128>>>(nullptr, nullptr, x, g2, nullptr, h);

    // 8. SwiGLU FFN: u = h@Wu ; gu = silu(h@Wg)*u ; x += gu@Wd
    gemm(h, Wu, u, nullptr, NTOK, DMODEL, DFF, EPI_NONE);
    gemm(h, Wg, gu, u, NTOK, DMODEL, DFF, EPI_SILU);
    gemm(gu, Wd, x, x, NTOK, DFF, DMODEL, EPI_RES);

    // 9. mean pool + head
    {
        dim3 gpool(DMODEL / 64, BATCH);
        pool_kernel<<<gpool, 256>>>(x, xm);
    }
    head_kernel<<<1, 512>>>(xm, Wc, bc, out);
}

// round 2
// speedup vs baseline: 2.7582x; 2.7582x over previous
#include <cuda_runtime.h>
#include <cuda_fp16.h>
#include <cuda_pipeline.h>
#include <mma.h>
#include <math.h>

using namespace nvcuda;

// ---------------- problem constants ----------------
#define NTOK   65536      // B*S = 8*8192
#define BATCH  8
#define SEQ    8192
#define DMODEL 512
#define NHEAD  8
#define NKV    2
#define DHEAD  64
#define MFEAT  64
#define DFF    2048
#define NCLS   2
#define EPSV   1e-6f

// ---------------- scratch (static device allocations only) ----------------
__device__ float  g_x   [NTOK * DMODEL];          // residual stream (fp32)
__device__ __half g_h   [NTOK * DMODEL];          // rmsnorm output
__device__ __half g_qkv [NTOK * (DMODEL + 2*128)];// q | k | v regions
__device__ __half g_pq  [NTOK * NHEAD * MFEAT];
__device__ __half g_pk  [NTOK * NKV  * MFEAT];
__device__ __half g_att [NTOK * DMODEL];
__device__ __half g_gu  [NTOK * DFF];
__device__ float  g_kvp [128 * 64 * 65];          // 16 pairs * 8 chunks
__device__ float  g_kv  [16 * 64 * 65];
__device__ float  g_xm  [BATCH * DMODEL];
// converted weights
__device__ __half g_WqkvH[DMODEL * 768];
__device__ __half g_WphiH[DHEAD * MFEAT];
__device__ __half g_WoH  [DMODEL * DMODEL];
__device__ __half g_WguH [DMODEL * (2*DFF)];      // interleaved g,u columns
__device__ __half g_WdH  [DFF * DMODEL];

struct alignas(8) half4 { __half2 a, b; };
__device__ __forceinline__ half4 f4_to_h4(float4 v) {
    half4 r; r.a = __floats2half2_rn(v.x, v.y); r.b = __floats2half2_rn(v.z, v.w); return r;
}

// ---------------- weight conversion ----------------
__global__ void conv_qkv_w(const float* __restrict__ Wq, const float* __restrict__ Wk,
                           const float* __restrict__ Wv, __half* __restrict__ W) {
    int idx = blockIdx.x * 256 + threadIdx.x;          // 512*768
    int r = idx / 768, c = idx % 768;
    float v = (c < 512) ? Wq[r * 512 + c] : (c < 640 ? Wk[r * 128 + c - 512]
                                                     : Wv[r * 128 + c - 640]);
    W[idx] = __float2half(v);
}
__global__ void conv_gu_w(const float* __restrict__ Wg, const float* __restrict__ Wu,
                          __half* __restrict__ W) {
    int idx = blockIdx.x * 256 + threadIdx.x;          // 512*4096
    int r = idx >> 12, c = idx & 4095;
    int j = c >> 1;
    float v = (c & 1) ? Wu[r * DFF + j] : Wg[r * DFF + j];
    W[idx] = __float2half(v);
}
__global__ void conv_f2h(const float* __restrict__ src, __half* __restrict__ dst, int n) {
    int idx = blockIdx.x * 256 + threadIdx.x;
    if (idx < n) dst[idx] = __float2half(src[idx]);
}

// ---------------- fp16 double-buffered WMMA GEMM ----------------
// C[M,Nc] = A[M,K] @ B[K,Nc]; BM=128, BK=32, BN template (128 or 64).
#define EPI_QKV    0   // half out, split into q|k|v regions
#define EPI_EXPABS 1   // half out, exp(-|acc|)
#define EPI_RES    2   // fp32 out, acc + X
#define EPI_SWIGLU 3   // half out, interleaved cols -> silu(g)*u, Nout = Nc/2

template<int BN, int EPI>
__global__ __launch_bounds__(256) void gemm_h(
    const __half* __restrict__ A, const __half* __restrict__ B,
    void* __restrict__ Cout, const float* __restrict__ X,
    int M, int K, int Nc)
{
    constexpr int BM = 128, BK = 32;
    constexpr int LDA_S = BK + 8;       // 40 halves
    constexpr int LDB_S = BN + 8;       // 136 / 72
    constexpr int LDC_S = BN + 4;
    constexpr int NF = BN / 32;         // n-frags per warp (warp tile 32 x BN/2)

    extern __shared__ __align__(16) char smem_raw[];
    __half* As0 = (__half*)smem_raw;
    __half* As1 = As0 + BM * LDA_S;
    __half* Bs0 = As1 + BM * LDA_S;
    __half* Bs1 = Bs0 + BK * LDB_S;
    __half* Asb[2] = {As0, As1};
    __half* Bsb[2] = {Bs0, Bs1};

    const int tid  = threadIdx.x;
    const int bm   = blockIdx.x * BM;
    const int bn   = blockIdx.y * BN;
    const int warp = tid >> 5;
    const int wm   = (warp >> 1) * 32;
    const int wn   = (warp & 1) * (BN / 2);

    wmma::fragment<wmma::accumulator, 16, 16, 16, float> c[2][NF];
#pragma unroll
    for (int i = 0; i < 2; i++)
#pragma unroll
        for (int j = 0; j < NF; j++) wmma::fill_fragment(c[i][j], 0.0f);

    auto load_stage = [&](int kt, int s) {
        // A tile: 128x32 halves, 512 chunks of 16B, 2 per thread
#pragma unroll
        for (int i = 0; i < 2; i++) {
            int idx = tid + i * 256;
            int r  = idx >> 2;
            int cc = (idx & 3) * 8;
            __pipeline_memcpy_async(&Asb[s][r * LDA_S + cc],
                                    &A[(size_t)(bm + r) * K + kt + cc], 16);
        }
        // B tile: 32xBN halves
        constexpr int CH = BN / 8;
        constexpr int NB = (BK * CH) / 256;
#pragma unroll
        for (int i = 0; i < NB; i++) {
            int idx = tid + i * 256;
            int r  = idx / CH;
            int cc = (idx % CH) * 8;
            __pipeline_memcpy_async(&Bsb[s][r * LDB_S + cc],
                                    &B[(size_t)(kt + r) * Nc + bn + cc], 16);
        }
    };

    load_stage(0, 0);
    __pipeline_commit();
    int s = 0;
    for (int kt = 0; kt < K; kt += BK) {
        if (kt + BK < K) {
            load_stage(kt + BK, s ^ 1);
            __pipeline_commit();
            __pipeline_wait_prior(1);
        } else {
            __pipeline_wait_prior(0);
        }
        __syncthreads();
#pragma unroll
        for (int kk = 0; kk < BK; kk += 16) {
            wmma::fragment<wmma::matrix_a, 16, 16, 16, __half, wmma::row_major> a[2];
            wmma::fragment<wmma::matrix_b, 16, 16, 16, __half, wmma::row_major> b[NF];
#pragma unroll
            for (int i = 0; i < 2; i++)
                wmma::load_matrix_sync(a[i], &Asb[s][(wm + i * 16) * LDA_S + kk], LDA_S);
#pragma unroll
            for (int j = 0; j < NF; j++)
                wmma::load_matrix_sync(b[j], &Bsb[s][kk * LDB_S + wn + j * 16], LDB_S);
#pragma unroll
            for (int i = 0; i < 2; i++)
#pragma unroll
                for (int j = 0; j < NF; j++)
                    wmma::mma_sync(c[i][j], a[i], b[j], c[i][j]);
        }
        __syncthreads();
        s ^= 1;
    }

    // stage accumulators to smem
    float* Cs = (float*)smem_raw;
#pragma unroll
    for (int i = 0; i < 2; i++)
#pragma unroll
        for (int j = 0; j < NF; j++)
            wmma::store_matrix_sync(&Cs[(wm + i * 16) * LDC_S + wn + j * 16], c[i][j],
                                    LDC_S, wmma::mem_row_major);
    __syncthreads();

    constexpr int NIT = (BM * BN / 4) / 256;     // float4s per thread
    constexpr int F4R = BN / 4;                   // float4s per row
#pragma unroll
    for (int i = 0; i < NIT; i++) {
        int e  = tid + i * 256;
        int r  = e / F4R;
        int cc = (e % F4R) * 4;
        float4 vv = *(float4*)&Cs[r * LDC_S + cc];
        if (EPI == EPI_QKV) {
            __half* dst; int ld, c0;
            if (bn < 512)      { dst = (__half*)Cout;                    ld = 512; c0 = bn; }
            else if (bn < 640) { dst = (__half*)Cout + (size_t)M * 512;  ld = 128; c0 = bn - 512; }
            else               { dst = (__half*)Cout + (size_t)M * 640;  ld = 128; c0 = bn - 640; }
            *(half4*)&dst[(size_t)(bm + r) * ld + c0 + cc] = f4_to_h4(vv);
        } else if (EPI == EPI_EXPABS) {
            vv.x = expf(-fabsf(vv.x)); vv.y = expf(-fabsf(vv.y));
            vv.z = expf(-fabsf(vv.z)); vv.w = expf(-fabsf(vv.w));
            *(half4*)&((__half*)Cout)[(size_t)(bm + r) * Nc + bn + cc] = f4_to_h4(vv);
        } else if (EPI == EPI_RES) {
            size_t gidx = (size_t)(bm + r) * Nc + bn + cc;
            float4 xv = *(const float4*)&X[gidx];
            vv.x += xv.x; vv.y += xv.y; vv.z += xv.z; vv.w += xv.w;
            *(float4*)&((float*)Cout)[gidx] = vv;
        } else { // EPI_SWIGLU: (g0,u0,g1,u1) -> 2 halves
            float s0 = vv.x / (1.0f + expf(-vv.x)) * vv.y;
            float s1 = vv.z / (1.0f + expf(-vv.z)) * vv.w;
            int jo = (bn + cc) >> 1;
            *(__half2*)&((__half*)Cout)[(size_t)(bm + r) * (Nc >> 1) + jo] =
                __floats2half2_rn(s0, s1);
        }
    }
}

// ---------------- gather + rmsnorm (also plain rmsnorm); h out is half ----------------
__global__ __launch_bounds__(128) void gather_rmsnorm_kernel(
    const int* __restrict__ ids, const float* __restrict__ emb,
    const float* __restrict__ xin, const float* __restrict__ g,
    float* __restrict__ xout, __half* __restrict__ h)
{
    int token = blockIdx.x;
    const float* src = ids ? (emb + (size_t)ids[token] * DMODEL)
                           : (xin + (size_t)token * DMODEL);
    int c = threadIdx.x * 4;
    float4 v = *(const float4*)&src[c];
    float ss = v.x * v.x + v.y * v.y + v.z * v.z + v.w * v.w;
#pragma unroll
    for (int off = 16; off > 0; off >>= 1) ss += __shfl_xor_sync(0xffffffffu, ss, off);
    __shared__ float sred[4];
    int warp = threadIdx.x >> 5, lane = threadIdx.x & 31;
    if (lane == 0) sred[warp] = ss;
    __syncthreads();
    float tot = sred[0] + sred[1] + sred[2] + sred[3];
    float scale = rsqrtf(tot * (1.0f / DMODEL) + EPSV);
    float4 gv = *(const float4*)&g[c];
    float4 o;
    o.x = v.x * scale * gv.x; o.y = v.y * scale * gv.y;
    o.z = v.z * scale * gv.z; o.w = v.w * scale * gv.w;
    if (xout) *(float4*)&xout[(size_t)token * DMODEL + c] = v;
    *(half4*)&h[(size_t)token * DMODEL + c] = f4_to_h4(o);
}

// ---------------- kv state: kv[b,kh,m,d] = sum_s pk*v ; col 64 = z ----------------
__global__ __launch_bounds__(256) void kv_partial_kernel(
    const __half* __restrict__ pk, const __half* __restrict__ v, float* __restrict__ kvp)
{
    int pair = blockIdx.x;            // b*2+kh
    int chunk = blockIdx.y;           // 0..7
    int b = pair >> 1, kh = pair & 1;
    int tid = threadIdx.x;
    int ti = tid >> 4, tj = tid & 15;
    float acc[4][4];
    float zacc[4];
#pragma unroll
    for (int a = 0; a < 4; a++) { zacc[a] = 0.f;
#pragma unroll
        for (int bb = 0; bb < 4; bb++) acc[a][bb] = 0.f; }

    __shared__ float spk[4][64], sv[4][64];
    int s0 = chunk * 1024;
    int tok = tid >> 6, lane = tid & 63;
    for (int sb = 0; sb < 1024; sb += 4) {
        int token = b * SEQ + s0 + sb + tok;
        size_t base = ((size_t)token * NKV + kh) * 64 + lane;
        spk[tok][lane] = __half2float(pk[base]);
        sv[tok][lane]  = __half2float(v[base]);
        __syncthreads();
#pragma unroll
        for (int t = 0; t < 4; t++) {
            float pm[4], vd[4];
#pragma unroll
            for (int mm = 0; mm < 4; mm++) pm[mm] = spk[t][ti * 4 + mm];
#pragma unroll
            for (int dd = 0; dd < 4; dd++) vd[dd] = sv[t][tj * 4 + dd];
#pragma unroll
            for (int mm = 0; mm < 4; mm++) {
#pragma unroll
                for (int dd = 0; dd < 4; dd++) acc[mm][dd] = fmaf(pm[mm], vd[dd], acc[mm][dd]);
                if (tj == 0) zacc[mm] += pm[mm];
            }
        }
        __syncthreads();
    }
    int pc = pair * 8 + chunk;
#pragma unroll
    for (int mm = 0; mm < 4; mm++) {
#pragma unroll
        for (int dd = 0; dd < 4; dd++)
            kvp[(size_t)pc * 4160 + (ti * 4 + mm) * 65 + tj * 4 + dd] = acc[mm][dd];
        if (tj == 0) kvp[(size_t)pc * 4160 + (ti * 4 + mm) * 65 + 64] = zacc[mm];
    }
}

__global__ __launch_bounds__(256) void kv_reduce_kernel(
    const float* __restrict__ kvp, float* __restrict__ kv)
{
    int pair = blockIdx.x;
    for (int idx = threadIdx.x; idx < 4160; idx += 256) {
        float s = 0.f;
#pragma unroll
        for (int c = 0; c < 8; c++) s += kvp[(size_t)(pair * 8 + c) * 4160 + idx];
        kv[(size_t)pair * 4160 + idx] = s;
    }
}

// ---------------- num/den: attn = (pq @ kv) / (pq @ z + eps) ----------------
__global__ __launch_bounds__(256) void numden_kernel(
    const __half* __restrict__ pq, const float* __restrict__ kvg, __half* __restrict__ att)
{
    int b = blockIdx.y;
    __shared__ float skv[2 * 64 * 65];
    __shared__ float spq[4][64];
    for (int idx = threadIdx.x; idx < 8320; idx += 256)
        skv[idx] = kvg[(size_t)b * 8320 + idx];
    __syncthreads();

    int group = threadIdx.x >> 6, lane = threadIdx.x & 63;
    int base = blockIdx.x * 128;
    for (int it = 0; it < 32; it++) {
        int th = base + it * 4 + group;          // th = s*8 + h
        size_t row = ((size_t)b * (SEQ * NHEAD) + th) * 64;
        spq[group][lane] = __half2float(pq[row + lane]);
        __syncthreads();
        int h = th & 7;
        const float* kvh = &skv[(h >> 2) * 4160];
        float num = 0.f, den = 0.f;
#pragma unroll
        for (int m = 0; m < 64; m++) {
            float p = spq[group][m];
            num = fmaf(p, kvh[m * 65 + lane], num);
            den = fmaf(p, kvh[m * 65 + 64], den);
        }
        att[row + lane] = __float2half(num / (den + EPSV));
        __syncthreads();
    }
}

// ---------------- mean pool over sequence ----------------
__global__ __launch_bounds__(256) void pool_kernel(
    const float* __restrict__ x, float* __restrict__ xm)
{
    int b = blockIdx.y;
    int c = blockIdx.x * 64 + (threadIdx.x & 63);
    int part = threadIdx.x >> 6;
    float s = 0.f;
    for (int t = part; t < SEQ; t += 4)
        s += x[((size_t)b * SEQ + t) * DMODEL + c];
    __shared__ float red[4][64];
    red[part][threadIdx.x & 63] = s;
    __syncthreads();
    if (part == 0) {
        int l = threadIdx.x & 63;
        xm[b * DMODEL + c] = red[0][l] + red[1][l] + red[2][l] + red[3][l];
    }
}

// ---------------- classifier head ----------------
__global__ __launch_bounds__(512) void head_kernel(
    const float* __restrict__ xm, const float* __restrict__ Wc,
    const float* __restrict__ bc, float* __restrict__ out)
{
    int warp = threadIdx.x >> 5, lane = threadIdx.x & 31;
    int b = warp >> 1, cls = warp & 1;
    float s = 0.f;
    for (int d = lane; d < DMODEL; d += 32)
        s += xm[b * DMODEL + d] * Wc[d * NCLS + cls];
#pragma unroll
    for (int off = 16; off > 0; off >>= 1) s += __shfl_xor_sync(0xffffffffu, s, off);
    if (lane == 0) out[b * NCLS + cls] = s * (1.0f / SEQ) + bc[cls];
}

// ---------------- launch ----------------
#define SMEM_BN128 (128 * 132 * 4)   // 67584 (epilogue dominates)
#define SMEM_BN64  (128 * 68 * 4)    // 34816

extern "C" void kernel_launch(void* const* d_in, const int* in_sizes, int n_in,
                              void* d_out, int out_size)
{
    (void)in_sizes; (void)n_in; (void)out_size;
    const int*   ids  = (const int*)  d_in[0];
    const float* emb  = (const float*)d_in[1];
    const float* Wq   = (const float*)d_in[2];
    const float* Wk   = (const float*)d_in[3];
    const float* Wv   = (const float*)d_in[4];
    const float* Wphi = (const float*)d_in[5];
    const float* Wo   = (const float*)d_in[6];
    const float* g1   = (const float*)d_in[7];
    const float* g2   = (const float*)d_in[8];
    const float* Wg   = (const float*)d_in[9];
    const float* Wu   = (const float*)d_in[10];
    const float* Wd   = (const float*)d_in[11];
    const float* Wc   = (const float*)d_in[12];
    const float* bc   = (const float*)d_in[13];
    float* out = (float*)d_out;

    float *x, *kvp, *kv, *xm;
    __half *h, *qkv, *pq, *pk, *att, *gu;
    __half *WqkvH, *WphiH, *WoH, *WguH, *WdH;
    cudaGetSymbolAddress((void**)&x,    g_x);
    cudaGetSymbolAddress((void**)&h,    g_h);
    cudaGetSymbolAddress((void**)&qkv,  g_qkv);
    cudaGetSymbolAddress((void**)&pq,   g_pq);
    cudaGetSymbolAddress((void**)&pk,   g_pk);
    cudaGetSymbolAddress((void**)&att,  g_att);
    cudaGetSymbolAddress((void**)&gu,   g_gu);
    cudaGetSymbolAddress((void**)&kvp,  g_kvp);
    cudaGetSymbolAddress((void**)&kv,   g_kv);
    cudaGetSymbolAddress((void**)&xm,   g_xm);
    cudaGetSymbolAddress((void**)&WqkvH, g_WqkvH);
    cudaGetSymbolAddress((void**)&WphiH, g_WphiH);
    cudaGetSymbolAddress((void**)&WoH,   g_WoH);
    cudaGetSymbolAddress((void**)&WguH,  g_WguH);
    cudaGetSymbolAddress((void**)&WdH,   g_WdH);

    cudaFuncSetAttribute(gemm_h<128, EPI_QKV>,    cudaFuncAttributeMaxDynamicSharedMemorySize, SMEM_BN128);
    cudaFuncSetAttribute(gemm_h<128, EPI_RES>,    cudaFuncAttributeMaxDynamicSharedMemorySize, SMEM_BN128);
    cudaFuncSetAttribute(gemm_h<128, EPI_SWIGLU>, cudaFuncAttributeMaxDynamicSharedMemorySize, SMEM_BN128);

    // 0. weight conversion (fp32 -> fp16, with concat / interleave)
    conv_qkv_w<<<512 * 768 / 256, 256>>>(Wq, Wk, Wv, WqkvH);
    conv_gu_w<<<512 * 4096 / 256, 256>>>(Wg, Wu, WguH);
    conv_f2h<<<(DHEAD * MFEAT + 255) / 256, 256>>>(Wphi, WphiH, DHEAD * MFEAT);
    conv_f2h<<<(DMODEL * DMODEL + 255) / 256, 256>>>(Wo, WoH, DMODEL * DMODEL);
    conv_f2h<<<(DFF * DMODEL + 255) / 256, 256>>>(Wd, WdH, DFF * DMODEL);

    // 1. embedding gather + rmsnorm (writes x fp32 and h fp16)
    gather_rmsnorm_kernel<<<NTOK, 128>>>(ids, emb, nullptr, g1, x, h);

    // 2. fused qkv projection: [NTOK,512] @ [512,768] -> q|k|v
    {
        dim3 grid(NTOK / 128, 768 / 128);
        gemm_h<128, EPI_QKV><<<grid, 256, SMEM_BN128>>>(h, WqkvH, qkv, nullptr, NTOK, DMODEL, 768);
    }

    // 3. Laplacian feature maps (BN=64)
    {
        dim3 gq(NTOK * NHEAD / 128, 1);
        gemm_h<64, EPI_EXPABS><<<gq, 256, SMEM_BN64>>>(qkv, WphiH, pq, nullptr, NTOK * NHEAD, DHEAD, MFEAT);
        dim3 gk(NTOK * NKV / 128, 1);
        gemm_h<64, EPI_EXPABS><<<gk, 256, SMEM_BN64>>>(qkv + (size_t)NTOK * 512, WphiH, pk, nullptr, NTOK * NKV, DHEAD, MFEAT);
    }

    // 4. global kv state + normalizer
    {
        dim3 gp(BATCH * NKV, 8);
        kv_partial_kernel<<<gp, 256>>>(pk, qkv + (size_t)NTOK * 640, kvp);
        kv_reduce_kernel<<<BATCH * NKV, 256>>>(kvp, kv);
    }

    // 5. num/den -> attn (fp16)
    {
        dim3 gn(SEQ * NHEAD / 128, BATCH);
        numden_kernel<<<gn, 256>>>(pq, kv, att);
    }

    // 6. output projection + residual (fp32 x in-place)
    {
        dim3 grid(NTOK / 128, DMODEL / 128);
        gemm_h<128, EPI_RES><<<grid, 256, SMEM_BN128>>>(att, WoH, x, x, NTOK, DMODEL, DMODEL);
    }

    // 7. pre-FFN rmsnorm
    gather_rmsnorm_kernel<<<NTOK, 128>>>(nullptr, nullptr, x, g2, nullptr, h);

    // 8. fused SwiGLU FFN up: [NTOK,512] @ [512,4096 interleaved] -> gu (fp16)
    {
        dim3 grid(NTOK / 128, 4096 / 128);
        gemm_h<128, EPI_SWIGLU><<<grid, 256, SMEM_BN128>>>(h, WguH, gu, nullptr, NTOK, DMODEL, 4096);
    }
    // 9. down proj + residual
    {
        dim3 grid(NTOK / 128, DMODEL / 128);
        gemm_h<128, EPI_RES><<<grid, 256, SMEM_BN128>>>(gu, WdH, x, x, NTOK, DFF, DMODEL);
    }

    // 10. mean pool + head
    {
        dim3 gpool(DMODEL / 64, BATCH);
        pool_kernel<<<gpool, 256>>>(x, xm);
    }
    head_kernel<<<1, 512>>>(xm, Wc, bc, out);
}

// round 6
// speedup vs baseline: 3.5847x; 1.2997x over previous
#include <cuda_runtime.h>
#include <cuda_fp16.h>
#include <cuda_pipeline.h>
#include <mma.h>
#include <math.h>
#include <cstdint>

using namespace nvcuda;

// ---------------- problem constants ----------------
#define NTOK   65536
#define BATCH  8
#define SEQ    8192
#define DMODEL 512
#define NHEAD  8
#define NKV    2
#define DHEAD  64
#define MFEAT  64
#define DFF    2048
#define NCLS   2
#define EPSV   1e-6f

// ---------------- scratch ----------------
__device__ float  g_x   [NTOK * DMODEL];
__device__ __half g_h   [NTOK * DMODEL];
__device__ __half g_qkv [NTOK * (DMODEL + 2*128)];
__device__ __half g_pq  [NTOK * NHEAD * MFEAT];
__device__ __half g_pk  [NTOK * NKV  * MFEAT];
__device__ __half g_att [NTOK * DMODEL];
__device__ __half g_gu  [NTOK * DFF];
__device__ float  g_kvp [128 * 64 * 65];
__device__ float  g_kv  [16 * 64 * 65];
__device__ float  g_xm  [BATCH * DMODEL];
// converted fp16 weights, row-major [K, N]
__device__ __half g_WqkvH[DMODEL * 768];
__device__ __half g_WphiH[DHEAD * MFEAT];
__device__ __half g_WoH  [DMODEL * DMODEL];
__device__ __half g_WguH [DMODEL * (2*DFF)];   // interleaved g,u columns
__device__ __half g_WdH  [DFF * DMODEL];

struct alignas(8) half4 { __half2 a, b; };
__device__ __forceinline__ half4 f4_to_h4(float4 v) {
    half4 r; r.a = __floats2half2_rn(v.x, v.y); r.b = __floats2half2_rn(v.z, v.w); return r;
}

// ---------------- weight conversion ----------------
__global__ void conv_qkv_w(const float* __restrict__ Wq, const float* __restrict__ Wk,
                           const float* __restrict__ Wv, __half* __restrict__ W) {
    int idx = blockIdx.x * 256 + threadIdx.x;          // 512*768
    int r = idx / 768, c = idx % 768;
    float v = (c < 512) ? Wq[r * 512 + c] : (c < 640 ? Wk[r * 128 + c - 512]
                                                     : Wv[r * 128 + c - 640]);
    W[idx] = __float2half(v);
}
__global__ void conv_gu_w(const float* __restrict__ Wg, const float* __restrict__ Wu,
                          __half* __restrict__ W) {
    int idx = blockIdx.x * 256 + threadIdx.x;          // 512*4096
    int r = idx >> 12, c = idx & 4095;
    int j = c >> 1;
    float v = (c & 1) ? Wu[r * DFF + j] : Wg[r * DFF + j];
    W[idx] = __float2half(v);
}
__global__ void conv_f2h(const float* __restrict__ src, __half* __restrict__ dst, int n) {
    int idx = blockIdx.x * 256 + threadIdx.x;
    if (idx < n) dst[idx] = __float2half(src[idx]);
}

// ---------------- fp16 multi-stage WMMA GEMM ----------------
// C[M,Nc] = A[M,K] @ B[K,Nc]; BM=128, BK=32, 4 stages, BN template (128 or 64).
#define EPI_QKV    0   // half out, split into q|k|v regions
#define EPI_EXPABS 1   // half out, exp(-|acc|)
#define EPI_RES    2   // fp32 out, acc + X
#define EPI_SWIGLU 3   // half out, interleaved cols -> silu(g)*u, Nout = Nc/2
#define STAGES 4

template<int BN, int EPI>
__global__ __launch_bounds__(256, 2) void gemm_h(
    const __half* __restrict__ A, const __half* __restrict__ B,
    void* __restrict__ Cout, const float* __restrict__ X,
    int M, int K, int Nc)
{
    constexpr int BM = 128, BK = 32;
    constexpr int LDA_S = BK + 8;       // 40 halves
    constexpr int LDB_S = BN + 8;       // 136 / 72
    constexpr int LDC_S = BN + 4;       // floats
    constexpr int NF = BN / 32;         // n-frags per warp (warp tile 32 x BN/2)
    constexpr int A_ELE = BM * LDA_S;   // halves per A stage
    constexpr int B_ELE = BK * LDB_S;
    constexpr int STG_ELE = A_ELE + B_ELE;

    extern __shared__ __align__(16) char smem_raw[];
    __half* stg = (__half*)smem_raw;

    const int tid  = threadIdx.x;
    const int bm   = blockIdx.x * BM;
    const int bn   = blockIdx.y * BN;
    const int warp = tid >> 5;
    const int wm   = (warp >> 1) * 32;
    const int wn   = (warp & 1) * (BN / 2);

    wmma::fragment<wmma::accumulator, 16, 16, 16, float> c[2][NF];
#pragma unroll
    for (int i = 0; i < 2; i++)
#pragma unroll
        for (int j = 0; j < NF; j++) wmma::fill_fragment(c[i][j], 0.0f);

    const int nK = K / BK;

    auto load_stage = [&](int kt, int s) {
        __half* As = stg + s * STG_ELE;
        __half* Bs = As + A_ELE;
        // A tile: 128x32 halves = 512 16B-chunks, 2 per thread
#pragma unroll
        for (int i = 0; i < 2; i++) {
            int idx = tid + i * 256;
            int r  = idx >> 2;
            int cc = (idx & 3) * 8;
            __pipeline_memcpy_async(&As[r * LDA_S + cc],
                                    &A[(size_t)(bm + r) * K + kt + cc], 16);
        }
        // B tile: 32xBN halves
        constexpr int CH = BN / 8;
        constexpr int NB = (BK * CH) / 256;
#pragma unroll
        for (int i = 0; i < NB; i++) {
            int idx = tid + i * 256;
            int r  = idx / CH;
            int cc = (idx % CH) * 8;
            __pipeline_memcpy_async(&Bs[r * LDB_S + cc],
                                    &B[(size_t)(kt + r) * Nc + bn + cc], 16);
        }
    };

    // prologue: fill STAGES-1 buffers (guarded for tiny K)
#pragma unroll
    for (int s = 0; s < STAGES - 1; s++) {
        if (s < nK) load_stage(s * BK, s);
        __pipeline_commit();
    }

    for (int kt_i = 0; kt_i < nK; kt_i++) {
        __pipeline_wait_prior(STAGES - 2);
        __syncthreads();
        int ldk = kt_i + STAGES - 1;
        if (ldk < nK) load_stage(ldk * BK, ldk % STAGES);
        __pipeline_commit();

        int s = kt_i % STAGES;
        __half* As = stg + s * STG_ELE;
        __half* Bs = As + A_ELE;
#pragma unroll
        for (int kk = 0; kk < BK; kk += 16) {
            wmma::fragment<wmma::matrix_a, 16, 16, 16, __half, wmma::row_major> a[2];
            wmma::fragment<wmma::matrix_b, 16, 16, 16, __half, wmma::row_major> b[NF];
#pragma unroll
            for (int i = 0; i < 2; i++)
                wmma::load_matrix_sync(a[i], &As[(wm + i * 16) * LDA_S + kk], LDA_S);
#pragma unroll
            for (int j = 0; j < NF; j++)
                wmma::load_matrix_sync(b[j], &Bs[kk * LDB_S + wn + j * 16], LDB_S);
#pragma unroll
            for (int i = 0; i < 2; i++)
#pragma unroll
                for (int j = 0; j < NF; j++)
                    wmma::mma_sync(c[i][j], a[i], b[j], c[i][j]);
        }
    }

    // epilogue in two 64-row halves through a small smem buffer
    float* Cs = (float*)smem_raw;                  // 64 * LDC_S floats
    constexpr int F4R = BN / 4;                    // float4 per row
    constexpr int NIT = (64 * F4R) / 256;          // per-thread float4s per half
#pragma unroll
    for (int hrow = 0; hrow < 2; hrow++) {
        __syncthreads();
        if ((wm >> 6) == hrow) {
#pragma unroll
            for (int i = 0; i < 2; i++)
#pragma unroll
                for (int j = 0; j < NF; j++)
                    wmma::store_matrix_sync(&Cs[((wm & 63) + i * 16) * LDC_S + wn + j * 16],
                                            c[i][j], LDC_S, wmma::mem_row_major);
        }
        __syncthreads();
#pragma unroll
        for (int i = 0; i < NIT; i++) {
            int e  = tid + i * 256;
            int r  = e / F4R;
            int cc = (e % F4R) * 4;
            float4 vv = *(float4*)&Cs[r * LDC_S + cc];
            int grow = bm + hrow * 64 + r;
            if (EPI == EPI_QKV) {
                __half* dst; int ld, c0;
                if (bn < 512)      { dst = (__half*)Cout;                    ld = 512; c0 = bn; }
                else if (bn < 640) { dst = (__half*)Cout + (size_t)M * 512;  ld = 128; c0 = bn - 512; }
                else               { dst = (__half*)Cout + (size_t)M * 640;  ld = 128; c0 = bn - 640; }
                *(half4*)&dst[(size_t)grow * ld + c0 + cc] = f4_to_h4(vv);
            } else if (EPI == EPI_EXPABS) {
                vv.x = expf(-fabsf(vv.x)); vv.y = expf(-fabsf(vv.y));
                vv.z = expf(-fabsf(vv.z)); vv.w = expf(-fabsf(vv.w));
                *(half4*)&((__half*)Cout)[(size_t)grow * Nc + bn + cc] = f4_to_h4(vv);
            } else if (EPI == EPI_RES) {
                size_t gidx = (size_t)grow * Nc + bn + cc;
                float4 xv = *(const float4*)&X[gidx];
                vv.x += xv.x; vv.y += xv.y; vv.z += xv.z; vv.w += xv.w;
                *(float4*)&((float*)Cout)[gidx] = vv;
            } else { // EPI_SWIGLU
                float s0 = vv.x / (1.0f + expf(-vv.x)) * vv.y;
                float s1 = vv.z / (1.0f + expf(-vv.z)) * vv.w;
                int jo = (bn + cc) >> 1;
                *(__half2*)&((__half*)Cout)[(size_t)grow * (Nc >> 1) + jo] =
                    __floats2half2_rn(s0, s1);
            }
        }
    }
}

// ---------------- gather + rmsnorm ----------------
__global__ __launch_bounds__(128) void gather_rmsnorm_kernel(
    const int* __restrict__ ids, const float* __restrict__ emb,
    const float* __restrict__ xin, const float* __restrict__ g,
    float* __restrict__ xout, __half* __restrict__ h)
{
    int token = blockIdx.x;
    const float* src = ids ? (emb + (size_t)ids[token] * DMODEL)
                           : (xin + (size_t)token * DMODEL);
    int c = threadIdx.x * 4;
    float4 v = *(const float4*)&src[c];
    float ss = v.x * v.x + v.y * v.y + v.z * v.z + v.w * v.w;
#pragma unroll
    for (int off = 16; off > 0; off >>= 1) ss += __shfl_xor_sync(0xffffffffu, ss, off);
    __shared__ float sred[4];
    int warp = threadIdx.x >> 5, lane = threadIdx.x & 31;
    if (lane == 0) sred[warp] = ss;
    __syncthreads();
    float tot = sred[0] + sred[1] + sred[2] + sred[3];
    float scale = rsqrtf(tot * (1.0f / DMODEL) + EPSV);
    float4 gv = *(const float4*)&g[c];
    float4 o;
    o.x = v.x * scale * gv.x; o.y = v.y * scale * gv.y;
    o.z = v.z * scale * gv.z; o.w = v.w * scale * gv.w;
    if (xout) *(float4*)&xout[(size_t)token * DMODEL + c] = v;
    *(half4*)&h[(size_t)token * DMODEL + c] = f4_to_h4(o);
}

// ---------------- kv state (16-token tiles) ----------------
__global__ __launch_bounds__(256) void kv_partial_kernel(
    const __half* __restrict__ pk, const __half* __restrict__ v, float* __restrict__ kvp)
{
    int pair = blockIdx.x, chunk = blockIdx.y;
    int b = pair >> 1, kh = pair & 1;
    int tid = threadIdx.x;
    int ti = tid >> 4, tj = tid & 15;
    float acc[4][4], zacc[4];
#pragma unroll
    for (int a = 0; a < 4; a++) { zacc[a] = 0.f;
#pragma unroll
        for (int bb = 0; bb < 4; bb++) acc[a][bb] = 0.f; }
    __shared__ float spk[16][64], sv[16][64];
    int s0 = chunk * 1024;
    for (int sb = 0; sb < 1024; sb += 16) {
#pragma unroll
        for (int j = 0; j < 4; j++) {
            int idx = tid + j * 256;
            int t = idx >> 6, lane = idx & 63;
            int token = b * SEQ + s0 + sb + t;
            size_t base = ((size_t)token * NKV + kh) * 64 + lane;
            spk[t][lane] = __half2float(pk[base]);
            sv[t][lane]  = __half2float(v[base]);
        }
        __syncthreads();
#pragma unroll
        for (int t = 0; t < 16; t++) {
            float pm[4], vd[4];
#pragma unroll
            for (int mm = 0; mm < 4; mm++) pm[mm] = spk[t][ti * 4 + mm];
#pragma unroll
            for (int dd = 0; dd < 4; dd++) vd[dd] = sv[t][tj * 4 + dd];
#pragma unroll
            for (int mm = 0; mm < 4; mm++) {
#pragma unroll
                for (int dd = 0; dd < 4; dd++) acc[mm][dd] = fmaf(pm[mm], vd[dd], acc[mm][dd]);
                if (tj == 0) zacc[mm] += pm[mm];
            }
        }
        __syncthreads();
    }
    int pc = pair * 8 + chunk;
#pragma unroll
    for (int mm = 0; mm < 4; mm++) {
#pragma unroll
        for (int dd = 0; dd < 4; dd++)
            kvp[(size_t)pc * 4160 + (ti * 4 + mm) * 65 + tj * 4 + dd] = acc[mm][dd];
        if (tj == 0) kvp[(size_t)pc * 4160 + (ti * 4 + mm) * 65 + 64] = zacc[mm];
    }
}

__global__ __launch_bounds__(256) void kv_reduce_kernel(
    const float* __restrict__ kvp, float* __restrict__ kv)
{
    int pair = blockIdx.x;
    for (int idx = threadIdx.x; idx < 4160; idx += 256) {
        float s = 0.f;
#pragma unroll
        for (int c = 0; c < 8; c++) s += kvp[(size_t)(pair * 8 + c) * 4160 + idx];
        kv[(size_t)pair * 4160 + idx] = s;
    }
}

// ---------------- num/den ----------------
__global__ __launch_bounds__(256) void numden_kernel(
    const __half* __restrict__ pq, const float* __restrict__ kvg, __half* __restrict__ att)
{
    int b = blockIdx.y;
    __shared__ float skv[2 * 64 * 65];
    __shared__ float spq[4][64];
    for (int idx = threadIdx.x; idx < 8320; idx += 256)
        skv[idx] = kvg[(size_t)b * 8320 + idx];
    __syncthreads();
    int group = threadIdx.x >> 6, lane = threadIdx.x & 63;
    int base = blockIdx.x * 128;
    for (int it = 0; it < 32; it++) {
        int th = base + it * 4 + group;
        size_t row = ((size_t)b * (SEQ * NHEAD) + th) * 64;
        spq[group][lane] = __half2float(pq[row + lane]);
        __syncthreads();
        int h = th & 7;
        const float* kvh = &skv[(h >> 2) * 4160];
        float num = 0.f, den = 0.f;
#pragma unroll
        for (int m = 0; m < 64; m++) {
            float p = spq[group][m];
            num = fmaf(p, kvh[m * 65 + lane], num);
            den = fmaf(p, kvh[m * 65 + 64], den);
        }
        att[row + lane] = __float2half(num / (den + EPSV));
        __syncthreads();
    }
}

// ---------------- pool + head ----------------
__global__ __launch_bounds__(256) void pool_kernel(
    const float* __restrict__ x, float* __restrict__ xm)
{
    int b = blockIdx.y;
    int c = blockIdx.x * 64 + (threadIdx.x & 63);
    int part = threadIdx.x >> 6;
    float s = 0.f;
    for (int t = part; t < SEQ; t += 4)
        s += x[((size_t)b * SEQ + t) * DMODEL + c];
    __shared__ float red[4][64];
    red[part][threadIdx.x & 63] = s;
    __syncthreads();
    if (part == 0) {
        int l = threadIdx.x & 63;
        xm[b * DMODEL + c] = red[0][l] + red[1][l] + red[2][l] + red[3][l];
    }
}

__global__ __launch_bounds__(512) void head_kernel(
    const float* __restrict__ xm, const float* __restrict__ Wc,
    const float* __restrict__ bc, float* __restrict__ out)
{
    int warp = threadIdx.x >> 5, lane = threadIdx.x & 31;
    int b = warp >> 1, cls = warp & 1;
    float s = 0.f;
    for (int d = lane; d < DMODEL; d += 32)
        s += xm[b * DMODEL + d] * Wc[d * NCLS + cls];
#pragma unroll
    for (int off = 16; off > 0; off >>= 1) s += __shfl_xor_sync(0xffffffffu, s, off);
    if (lane == 0) out[b * NCLS + cls] = s * (1.0f / SEQ) + bc[cls];
}

// ---------------- launch ----------------
#define STG128  (128 * 40 + 32 * 136)                 // halves per stage, BN=128
#define STG64   (128 * 40 + 32 * 72)
#define SMEM_BN128_V ((STAGES * STG128) * 2)          // 75776 bytes
#define SMEM_BN64_V  ((STAGES * STG64) * 2)           // 59392 bytes

extern "C" void kernel_launch(void* const* d_in, const int* in_sizes, int n_in,
                              void* d_out, int out_size)
{
    (void)in_sizes; (void)n_in; (void)out_size;
    const int*   ids  = (const int*)  d_in[0];
    const float* emb  = (const float*)d_in[1];
    const float* Wq   = (const float*)d_in[2];
    const float* Wk   = (const float*)d_in[3];
    const float* Wv   = (const float*)d_in[4];
    const float* Wphi = (const float*)d_in[5];
    const float* Wo   = (const float*)d_in[6];
    const float* g1   = (const float*)d_in[7];
    const float* g2   = (const float*)d_in[8];
    const float* Wg   = (const float*)d_in[9];
    const float* Wu   = (const float*)d_in[10];
    const float* Wd   = (const float*)d_in[11];
    const float* Wc   = (const float*)d_in[12];
    const float* bc   = (const float*)d_in[13];
    float* out = (float*)d_out;

    float *x, *kvp, *kv, *xm;
    __half *h, *qkv, *pq, *pk, *att, *gu;
    __half *WqkvH, *WphiH, *WoH, *WguH, *WdH;
    cudaGetSymbolAddress((void**)&x,    g_x);
    cudaGetSymbolAddress((void**)&h,    g_h);
    cudaGetSymbolAddress((void**)&qkv,  g_qkv);
    cudaGetSymbolAddress((void**)&pq,   g_pq);
    cudaGetSymbolAddress((void**)&pk,   g_pk);
    cudaGetSymbolAddress((void**)&att,  g_att);
    cudaGetSymbolAddress((void**)&gu,   g_gu);
    cudaGetSymbolAddress((void**)&kvp,  g_kvp);
    cudaGetSymbolAddress((void**)&kv,   g_kv);
    cudaGetSymbolAddress((void**)&xm,   g_xm);
    cudaGetSymbolAddress((void**)&WqkvH, g_WqkvH);
    cudaGetSymbolAddress((void**)&WphiH, g_WphiH);
    cudaGetSymbolAddress((void**)&WoH,   g_WoH);
    cudaGetSymbolAddress((void**)&WguH,  g_WguH);
    cudaGetSymbolAddress((void**)&WdH,   g_WdH);

    cudaFuncSetAttribute(gemm_h<128, EPI_QKV>,    cudaFuncAttributeMaxDynamicSharedMemorySize, SMEM_BN128_V);
    cudaFuncSetAttribute(gemm_h<128, EPI_RES>,    cudaFuncAttributeMaxDynamicSharedMemorySize, SMEM_BN128_V);
    cudaFuncSetAttribute(gemm_h<128, EPI_SWIGLU>, cudaFuncAttributeMaxDynamicSharedMemorySize, SMEM_BN128_V);
    cudaFuncSetAttribute(gemm_h<64,  EPI_EXPABS>, cudaFuncAttributeMaxDynamicSharedMemorySize, SMEM_BN64_V);

    // 0. weight conversion
    conv_qkv_w<<<512 * 768 / 256, 256>>>(Wq, Wk, Wv, WqkvH);
    conv_gu_w<<<512 * 4096 / 256, 256>>>(Wg, Wu, WguH);
    conv_f2h<<<(DHEAD * MFEAT + 255) / 256, 256>>>(Wphi, WphiH, DHEAD * MFEAT);
    conv_f2h<<<(DMODEL * DMODEL + 255) / 256, 256>>>(Wo, WoH, DMODEL * DMODEL);
    conv_f2h<<<(DFF * DMODEL + 255) / 256, 256>>>(Wd, WdH, DFF * DMODEL);

    // 1. embedding gather + rmsnorm
    gather_rmsnorm_kernel<<<NTOK, 128>>>(ids, emb, nullptr, g1, x, h);

    // 2. fused qkv projection
    {
        dim3 grid(NTOK / 128, 768 / 128);
        gemm_h<128, EPI_QKV><<<grid, 256, SMEM_BN128_V>>>(h, WqkvH, qkv, nullptr, NTOK, DMODEL, 768);
    }

    // 3. Laplacian feature maps (K=64)
    {
        dim3 gq(NTOK * NHEAD / 128, 1);
        gemm_h<64, EPI_EXPABS><<<gq, 256, SMEM_BN64_V>>>(qkv, WphiH, pq, nullptr, NTOK * NHEAD, DHEAD, MFEAT);
        dim3 gk(NTOK * NKV / 128, 1);
        gemm_h<64, EPI_EXPABS><<<gk, 256, SMEM_BN64_V>>>(qkv + (size_t)NTOK * 512, WphiH, pk, nullptr, NTOK * NKV, DHEAD, MFEAT);
    }

    // 4. global kv state
    {
        dim3 gp(BATCH * NKV, 8);
        kv_partial_kernel<<<gp, 256>>>(pk, qkv + (size_t)NTOK * 640, kvp);
        kv_reduce_kernel<<<BATCH * NKV, 256>>>(kvp, kv);
    }

    // 5. num/den -> attn
    {
        dim3 gn(SEQ * NHEAD / 128, BATCH);
        numden_kernel<<<gn, 256>>>(pq, kv, att);
    }

    // 6. output projection + residual
    {
        dim3 grid(NTOK / 128, DMODEL / 128);
        gemm_h<128, EPI_RES><<<grid, 256, SMEM_BN128_V>>>(att, WoH, x, x, NTOK, DMODEL, DMODEL);
    }

    // 7. pre-FFN rmsnorm
    gather_rmsnorm_kernel<<<NTOK, 128>>>(nullptr, nullptr, x, g2, nullptr, h);

    // 8. fused SwiGLU up
    {
        dim3 grid(NTOK / 128, 4096 / 128);
        gemm_h<128, EPI_SWIGLU><<<grid, 256, SMEM_BN128_V>>>(h, WguH, gu, nullptr, NTOK, DMODEL, 4096);
    }
    // 9. down proj + residual
    {
        dim3 grid(NTOK / 128, DMODEL / 128);
        gemm_h<128, EPI_RES><<<grid, 256, SMEM_BN128_V>>>(gu, WdH, x, x, NTOK, DFF, DMODEL);
    }

    // 10. mean pool + head
    {
        dim3 gpool(DMODEL / 64, BATCH);
        pool_kernel<<<gpool, 256>>>(x, xm);
    }
    head_kernel<<<1, 512>>>(xm, Wc, bc, out);
}